// round 13
// baseline (speedup 1.0000x reference)
#include <cuda_runtime.h>
#include <math.h>

#define CC 128
#define MID 8
#define SB 32      // blocks per spatial dim
#define SPD 64     // full spatial dim
#define NT 2048    // tiles = 2 * 32 * 32

#define TWO_SQRT2 2.8284271247461903f
#define GSCALE (TWO_SQRT2 / 32768.0f)

// scratch (allocation-free rule: __device__ globals)
__device__ float g_gp[NT * MID];                // per-tile gw1-projected rowsums (64 KB)
__device__ float g_gmod[2 * CC];                // global-MLP output
__device__ float g_hid[NT * MID * SB];          // [tile][m][w] hidden acts, post-relu (2 MB)

// ---------------------------------------------------------------------------
// Kernel A: one CTA (128 threads) per (b,d,h) tile. R8 load/MLP structure;
// final phase projects per-tile channel rowsums through gw1 (read via __ldg,
// no smem copy) -> 8 floats per tile. Resource-trimmed for occupancy.
// ---------------------------------------------------------------------------
__global__ __launch_bounds__(128, 9) void kA(const float* __restrict__ x,
                                             const float* __restrict__ lw1,
                                             const float* __restrict__ lb1,
                                             const float* __restrict__ gw1) {
    int tile = blockIdx.x;         // b*1024 + d*32 + h
    int b = tile >> 10;
    int d = (tile >> 5) & 31;
    int h = tile & 31;
    int t = threadIdx.x;
    int col = t & 15;
    int g   = t >> 4;              // 0..7

    __shared__ float s_lw1[MID * CC];     // 4 KB, pre-scaled by 2*sqrt2
    __shared__ float s_hp[8 * MID * SB];  // 8 KB hidden partials [g][m][w]
    __shared__ float s_gp[CC][17];        // 8.5 KB gap pair-sums, padded
    __shared__ float s_rs[CC];            // per-channel rowsums

    for (int i = t; i < MID * CC; i += 128) s_lw1[i] = TWO_SQRT2 * lw1[i];

    const float* xb = x + (size_t)b * CC * (SPD * SPD * SPD);
    const size_t row_off = (size_t)(2 * d) * SPD * SPD + (size_t)(2 * h) * SPD;

    // 16 front-batched corner loads -> registers
    float vx[16], vz[16];
    #pragma unroll
    for (int it = 0; it < 16; it++) {
        int c = it * 8 + g;
        float4 v = *(const float4*)(xb + (size_t)c * (SPD * SPD * SPD) + row_off + 4 * col);
        vx[it] = v.x;
        vz[it] = v.z;
    }

    __syncthreads();   // s_lw1 ready

    #pragma unroll
    for (int it = 0; it < 16; it++) {
        int c = it * 8 + g;
        s_gp[c][col] = vx[it] + vz[it];
    }

    float a0[MID], a1[MID];
    #pragma unroll
    for (int m = 0; m < MID; m++) { a0[m] = 0.f; a1[m] = 0.f; }
    #pragma unroll
    for (int it = 0; it < 16; it++) {
        int c = it * 8 + g;
        #pragma unroll
        for (int m = 0; m < MID; m++) {
            float wv = s_lw1[m * CC + c];
            a0[m] = fmaf(wv, vx[it], a0[m]);
            a1[m] = fmaf(wv, vz[it], a1[m]);
        }
    }
    {
        float* hp = s_hp + g * (MID * SB);
        #pragma unroll
        for (int m = 0; m < MID; m++) {
            hp[m * SB + 2 * col]     = a0[m];
            hp[m * SB + 2 * col + 1] = a1[m];
        }
    }
    __syncthreads();

    // per-channel rowsum -> smem (stride-17 rows: conflict-free)
    {
        float s = 0.f;
        #pragma unroll
        for (int i = 0; i < 16; i++) s += s_gp[t][i];
        s_rs[t] = s;
    }

    // hidden: 256 outputs, 2 per thread; 8-way cross-group add + bias + relu
    #pragma unroll
    for (int r = 0; r < 2; r++) {
        int idx = t + r * 128;         // m*32 + w
        int m = idx >> 5;
        float acc = lb1[m];
        #pragma unroll
        for (int gg = 0; gg < 8; gg++) acc += s_hp[gg * (MID * SB) + idx];
        g_hid[(size_t)tile * (MID * SB) + idx] = fmaxf(acc, 0.f);
    }
    __syncthreads();   // s_rs complete

    // gw1 projection: 8 threads, 128-dot each (gw1 via __ldg; L2-resident)
    if (t < MID) {
        float acc = 0.f;
        #pragma unroll 8
        for (int c = 0; c < CC; c++)
            acc = fmaf(__ldg(&gw1[t * CC + c]), s_rs[c], acc);
        g_gp[tile * MID + t] = acc * GSCALE;
    }
}

// ---------------------------------------------------------------------------
// Kernel B: reduce per-tile projections (64 KB) + finish global MLP.
// One CTA per batch, 1024 threads.
// ---------------------------------------------------------------------------
__global__ __launch_bounds__(1024) void kRedMLP(const float* __restrict__ gb1,
                                                const float* __restrict__ gw2,
                                                const float* __restrict__ gb2) {
    int b = blockIdx.x;
    int t = threadIdx.x;
    int m = t & 7;
    int k = t >> 3;                // 0..127

    __shared__ float s_part[32][MID];   // per-warp partials
    __shared__ float hid[MID];

    float acc = 0.f;
    #pragma unroll
    for (int j = 0; j < 8; j++)
        acc += g_gp[(b * 1024 + k + 128 * j) * MID + m];

    acc += __shfl_xor_sync(0xffffffffu, acc, 8);
    acc += __shfl_xor_sync(0xffffffffu, acc, 16);
    if ((t & 31) < 8) s_part[t >> 5][m] = acc;
    __syncthreads();

    if (t < MID) {
        float s = 0.f;
        #pragma unroll
        for (int wgi = 0; wgi < 32; wgi++) s += s_part[wgi][t];
        hid[t] = fmaxf(s + gb1[t], 0.f);
    }
    __syncthreads();

    if (t < CC) {
        float a = gb2[t];
        #pragma unroll
        for (int mm = 0; mm < MID; mm++) a = fmaf(gw2[t * MID + mm], hid[mm], a);
        g_gmod[b * CC + t] = a;
    }
}

// ---------------------------------------------------------------------------
// Kernel C: pure streaming blend — EXACT R8 shape (proven 77.5us).
// ---------------------------------------------------------------------------
__global__ __launch_bounds__(256) void kBlend(const float* __restrict__ x,
                                              const float* __restrict__ lw2,
                                              const float* __restrict__ lb2,
                                              float* __restrict__ out) {
    unsigned tid = blockIdx.x * 256u + threadIdx.x;   // 0 .. 4194303
    int w4 = tid & 15;
    int h  = (tid >> 4) & 31;
    int d  = (tid >> 9) & 31;
    int bc = tid >> 14;            // 0..255
    int c  = bc & 127;

    size_t tile = ((size_t)(bc >> 7) << 10) + (d << 5) + h;
    const float* hb = g_hid + tile * (MID * SB) + 2 * w4;
    float gl = g_gmod[bc] + __ldg(&lb2[c]);
    float a0 = gl, a1 = gl;
    #pragma unroll
    for (int m = 0; m < MID; m++) {
        float2 hv = *(const float2*)(hb + m * SB);
        float wm = __ldg(&lw2[c * MID + m]);
        a0 = fmaf(wm, hv.x, a0);
        a1 = fmaf(wm, hv.y, a1);
    }
    float g0 = 1.0f / (1.0f + __expf(-a0));
    float g1 = 1.0f / (1.0f + __expf(-a1));

    size_t base = ((size_t)bc * SPD + 2 * d) * (SPD * SPD)
                + (size_t)(2 * h) * SPD + 4 * w4;

    float4 r00 = __ldcs((const float4*)(x + base));
    float4 r01 = __ldcs((const float4*)(x + base + SPD));
    float4 r10 = __ldcs((const float4*)(x + base + SPD * SPD));
    float4 r11 = __ldcs((const float4*)(x + base + SPD * SPD + SPD));

    float m0 = (r00.x + r00.y + r01.x + r01.y + r10.x + r10.y + r11.x + r11.y) * 0.125f;
    float m1 = (r00.z + r00.w + r01.z + r01.w + r10.z + r10.w + r11.z + r11.w) * 0.125f;
    float om0 = (1.0f - g0) * m0;
    float om1 = (1.0f - g1) * m1;

    r00.x = fmaf(g0, r00.x, om0); r00.y = fmaf(g0, r00.y, om0);
    r01.x = fmaf(g0, r01.x, om0); r01.y = fmaf(g0, r01.y, om0);
    r10.x = fmaf(g0, r10.x, om0); r10.y = fmaf(g0, r10.y, om0);
    r11.x = fmaf(g0, r11.x, om0); r11.y = fmaf(g0, r11.y, om0);
    r00.z = fmaf(g1, r00.z, om1); r00.w = fmaf(g1, r00.w, om1);
    r01.z = fmaf(g1, r01.z, om1); r01.w = fmaf(g1, r01.w, om1);
    r10.z = fmaf(g1, r10.z, om1); r10.w = fmaf(g1, r10.w, om1);
    r11.z = fmaf(g1, r11.z, om1); r11.w = fmaf(g1, r11.w, om1);

    __stcs((float4*)(out + base),                   r00);
    __stcs((float4*)(out + base + SPD),             r01);
    __stcs((float4*)(out + base + SPD * SPD),       r10);
    __stcs((float4*)(out + base + SPD * SPD + SPD), r11);
}

// ---------------------------------------------------------------------------
extern "C" void kernel_launch(void* const* d_in, const int* in_sizes, int n_in,
                              void* d_out, int out_size) {
    const float* x   = (const float*)d_in[0];
    const float* gw1 = (const float*)d_in[1];
    const float* gb1 = (const float*)d_in[2];
    const float* gw2 = (const float*)d_in[3];
    const float* gb2 = (const float*)d_in[4];
    const float* lw1 = (const float*)d_in[5];
    const float* lb1 = (const float*)d_in[6];
    const float* lw2 = (const float*)d_in[7];
    const float* lb2 = (const float*)d_in[8];
    float* out = (float*)d_out;

    kA<<<NT, 128>>>(x, lw1, lb1, gw1);
    kRedMLP<<<2, 1024>>>(gb1, gw2, gb2);
    kBlend<<<16384, 256>>>(x, lw2, lb2, out);
}

// round 14
// speedup vs baseline: 1.1044x; 1.1044x over previous
#include <cuda_runtime.h>
#include <math.h>

#define CC 128
#define MID 8
#define SB 32      // blocks per spatial dim
#define SPD 64     // full spatial dim
#define NT 2048    // tiles = 2 * 32 * 32

#define TWO_SQRT2 2.8284271247461903f
#define GSCALE (TWO_SQRT2 / 32768.0f)

// scratch (allocation-free rule: __device__ globals)
__device__ float g_gp[NT * MID];                // per-tile gw1-projected rowsums (64 KB)
__device__ float g_gmod[2 * CC];                // global-MLP output
__device__ float g_hid[NT * MID * SB];          // [tile][m][w] hidden acts, post-relu (2 MB)

// ---------------------------------------------------------------------------
// Kernel A: one CTA (128 threads) per (b,d,h) tile. R8 load/hidden structure.
// gw1-projection computed as 8 extra "hidden rows" over the SAME registers
// (second FMA pass), reduced over w via half-warp shfl + 288B staging.
// No s_gp / s_rs: smem 16.6 KB.
// ---------------------------------------------------------------------------
__global__ __launch_bounds__(128) void kA(const float* __restrict__ x,
                                          const float* __restrict__ lw1,
                                          const float* __restrict__ lb1,
                                          const float* __restrict__ gw1) {
    int tile = blockIdx.x;         // b*1024 + d*32 + h
    int b = tile >> 10;
    int d = (tile >> 5) & 31;
    int h = tile & 31;
    int t = threadIdx.x;
    int col = t & 15;
    int g   = t >> 4;              // 0..7

    __shared__ float s_lw1[MID * CC];     // 4 KB, pre-scaled by 2*sqrt2
    __shared__ float s_gw1[MID * CC];     // 4 KB, pre-scaled by GSCALE
    __shared__ float s_hp[8 * MID * SB];  // 8 KB hidden partials [g][m][w]
    __shared__ float s_st[8][9];          // gw1-projection staging [g][m'], padded

    for (int i = t; i < MID * CC; i += 128) {
        s_lw1[i] = TWO_SQRT2 * lw1[i];
        s_gw1[i] = GSCALE * gw1[i];
    }

    const float* xb = x + (size_t)b * CC * (SPD * SPD * SPD);
    const size_t row_off = (size_t)(2 * d) * SPD * SPD + (size_t)(2 * h) * SPD;

    // 16 front-batched corner loads -> registers
    float vx[16], vz[16];
    #pragma unroll
    for (int it = 0; it < 16; it++) {
        int c = it * 8 + g;
        float4 v = *(const float4*)(xb + (size_t)c * (SPD * SPD * SPD) + row_off + 4 * col);
        vx[it] = v.x;
        vz[it] = v.z;
    }

    __syncthreads();   // smem weights ready

    // hidden partials (lw1 pass)
    {
        float a0[MID], a1[MID];
        #pragma unroll
        for (int m = 0; m < MID; m++) { a0[m] = 0.f; a1[m] = 0.f; }
        #pragma unroll
        for (int it = 0; it < 16; it++) {
            int c = it * 8 + g;
            #pragma unroll
            for (int m = 0; m < MID; m++) {
                float wv = s_lw1[m * CC + c];
                a0[m] = fmaf(wv, vx[it], a0[m]);
                a1[m] = fmaf(wv, vz[it], a1[m]);
            }
        }
        float* hp = s_hp + g * (MID * SB);
        #pragma unroll
        for (int m = 0; m < MID; m++) {
            hp[m * SB + 2 * col]     = a0[m];
            hp[m * SB + 2 * col + 1] = a1[m];
        }
    }

    // gw1 pass (registers reused), then reduce over w (16 cols) via shfl
    {
        float b0[MID], b1[MID];
        #pragma unroll
        for (int m = 0; m < MID; m++) { b0[m] = 0.f; b1[m] = 0.f; }
        #pragma unroll
        for (int it = 0; it < 16; it++) {
            int c = it * 8 + g;
            #pragma unroll
            for (int m = 0; m < MID; m++) {
                float wv = s_gw1[m * CC + c];
                b0[m] = fmaf(wv, vx[it], b0[m]);
                b1[m] = fmaf(wv, vz[it], b1[m]);
            }
        }
        #pragma unroll
        for (int m = 0; m < MID; m++) {
            float pm = b0[m] + b1[m];          // both w's of this thread
            #pragma unroll
            for (int o = 1; o < 16; o <<= 1)   // sum over 16 cols (half-warp)
                pm += __shfl_xor_sync(0xffffffffu, pm, o);
            if (col == 0) s_st[g][m] = pm;
        }
    }
    __syncthreads();

    // hidden: 256 outputs, 2 per thread; 8-way cross-group add + bias + relu
    #pragma unroll
    for (int r = 0; r < 2; r++) {
        int idx = t + r * 128;         // m*32 + w
        int m = idx >> 5;
        float acc = lb1[m];
        #pragma unroll
        for (int gg = 0; gg < 8; gg++) acc += s_hp[gg * (MID * SB) + idx];
        g_hid[(size_t)tile * (MID * SB) + idx] = fmaxf(acc, 0.f);
    }

    // gw1 projection output: 8 threads sum the 8 g-groups
    if (t < MID) {
        float s = 0.f;
        #pragma unroll
        for (int gg = 0; gg < 8; gg++) s += s_st[gg][t];
        g_gp[tile * MID + t] = s;      // GSCALE already folded into s_gw1
    }
}

// ---------------------------------------------------------------------------
// Kernel B: reduce per-tile projections (64 KB) + finish global MLP.
// One CTA per batch, 1024 threads. (R12 version — proven)
// ---------------------------------------------------------------------------
__global__ __launch_bounds__(1024) void kRedMLP(const float* __restrict__ gb1,
                                                const float* __restrict__ gw2,
                                                const float* __restrict__ gb2) {
    int b = blockIdx.x;
    int t = threadIdx.x;
    int m = t & 7;
    int k = t >> 3;                // 0..127

    __shared__ float s_part[32][MID];   // per-warp partials
    __shared__ float hid[MID];

    float acc = 0.f;
    #pragma unroll
    for (int j = 0; j < 8; j++)
        acc += g_gp[(b * 1024 + k + 128 * j) * MID + m];

    acc += __shfl_xor_sync(0xffffffffu, acc, 8);
    acc += __shfl_xor_sync(0xffffffffu, acc, 16);
    if ((t & 31) < 8) s_part[t >> 5][m] = acc;
    __syncthreads();

    if (t < MID) {
        float s = 0.f;
        #pragma unroll
        for (int wgi = 0; wgi < 32; wgi++) s += s_part[wgi][t];
        hid[t] = fmaxf(s + gb1[t], 0.f);
    }
    __syncthreads();

    if (t < CC) {
        float a = gb2[t];
        #pragma unroll
        for (int mm = 0; mm < MID; mm++) a = fmaf(gw2[t * MID + mm], hid[mm], a);
        g_gmod[b * CC + t] = a;
    }
}

// ---------------------------------------------------------------------------
// Kernel C: pure streaming blend — EXACT R8 shape (proven 77.5us).
// ---------------------------------------------------------------------------
__global__ __launch_bounds__(256) void kBlend(const float* __restrict__ x,
                                              const float* __restrict__ lw2,
                                              const float* __restrict__ lb2,
                                              float* __restrict__ out) {
    unsigned tid = blockIdx.x * 256u + threadIdx.x;   // 0 .. 4194303
    int w4 = tid & 15;
    int h  = (tid >> 4) & 31;
    int d  = (tid >> 9) & 31;
    int bc = tid >> 14;            // 0..255
    int c  = bc & 127;

    size_t tile = ((size_t)(bc >> 7) << 10) + (d << 5) + h;
    const float* hb = g_hid + tile * (MID * SB) + 2 * w4;
    float gl = g_gmod[bc] + __ldg(&lb2[c]);
    float a0 = gl, a1 = gl;
    #pragma unroll
    for (int m = 0; m < MID; m++) {
        float2 hv = *(const float2*)(hb + m * SB);
        float wm = __ldg(&lw2[c * MID + m]);
        a0 = fmaf(wm, hv.x, a0);
        a1 = fmaf(wm, hv.y, a1);
    }
    float g0 = 1.0f / (1.0f + __expf(-a0));
    float g1 = 1.0f / (1.0f + __expf(-a1));

    size_t base = ((size_t)bc * SPD + 2 * d) * (SPD * SPD)
                + (size_t)(2 * h) * SPD + 4 * w4;

    float4 r00 = __ldcs((const float4*)(x + base));
    float4 r01 = __ldcs((const float4*)(x + base + SPD));
    float4 r10 = __ldcs((const float4*)(x + base + SPD * SPD));
    float4 r11 = __ldcs((const float4*)(x + base + SPD * SPD + SPD));

    float m0 = (r00.x + r00.y + r01.x + r01.y + r10.x + r10.y + r11.x + r11.y) * 0.125f;
    float m1 = (r00.z + r00.w + r01.z + r01.w + r10.z + r10.w + r11.z + r11.w) * 0.125f;
    float om0 = (1.0f - g0) * m0;
    float om1 = (1.0f - g1) * m1;

    r00.x = fmaf(g0, r00.x, om0); r00.y = fmaf(g0, r00.y, om0);
    r01.x = fmaf(g0, r01.x, om0); r01.y = fmaf(g0, r01.y, om0);
    r10.x = fmaf(g0, r10.x, om0); r10.y = fmaf(g0, r10.y, om0);
    r11.x = fmaf(g0, r11.x, om0); r11.y = fmaf(g0, r11.y, om0);
    r00.z = fmaf(g1, r00.z, om1); r00.w = fmaf(g1, r00.w, om1);
    r01.z = fmaf(g1, r01.z, om1); r01.w = fmaf(g1, r01.w, om1);
    r10.z = fmaf(g1, r10.z, om1); r10.w = fmaf(g1, r10.w, om1);
    r11.z = fmaf(g1, r11.z, om1); r11.w = fmaf(g1, r11.w, om1);

    __stcs((float4*)(out + base),                   r00);
    __stcs((float4*)(out + base + SPD),             r01);
    __stcs((float4*)(out + base + SPD * SPD),       r10);
    __stcs((float4*)(out + base + SPD * SPD + SPD), r11);
}

// ---------------------------------------------------------------------------
extern "C" void kernel_launch(void* const* d_in, const int* in_sizes, int n_in,
                              void* d_out, int out_size) {
    const float* x   = (const float*)d_in[0];
    const float* gw1 = (const float*)d_in[1];
    const float* gb1 = (const float*)d_in[2];
    const float* gw2 = (const float*)d_in[3];
    const float* gb2 = (const float*)d_in[4];
    const float* lw1 = (const float*)d_in[5];
    const float* lb1 = (const float*)d_in[6];
    const float* lw2 = (const float*)d_in[7];
    const float* lb2 = (const float*)d_in[8];
    float* out = (float*)d_out;

    kA<<<NT, 128>>>(x, lw1, lb1, gw1);
    kRedMLP<<<2, 1024>>>(gb1, gw2, gb2);
    kBlend<<<16384, 256>>>(x, lw2, lb2, out);
}